// round 15
// baseline (speedup 1.0000x reference)
#include <cuda_runtime.h>
#include <cuda_bf16.h>
#include <math.h>
#include <stdint.h>

#define Bsz   256
#define Dm    256
#define Hh    8
#define HD    32
#define KTOP  10
#define CAP   500000

#define BN3    128           // holo rows per tile
#define NTILE  3907          // ceil(500000/128)
#define PADROWS ((size_t)NTILE * BN3)   // 500096
#define TCAND  4             // per-tile candidates kept per row
#define NCHK   4             // K chunks of 64
#define NSTG   3

#define TOTC   (NTILE * TCAND)          // 15628 candidates per row
#define SELR   24                       // radix-select rank
#define WCAP   48                       // rescore window capacity

// ---- sims kernel dynamic smem (bytes): 3 stages x (A 16KB + B 16KB) ----
#define STG_BYTES 32768
#define SMEM3     98304
// epilogue overlay
#define OFF_DS    0          // float [128][132] = 67584
#define OFF_LV    67584      // float [256][4]   = 4096
#define OFF_LI    71680      // int   [256][4]   = 4096
#define OFF_STR   75776      // float [128]

// ---------------- device scratch ----------------
__device__ __nv_bfloat16 g_holoBf[PADROWS * Dm];
__device__ int   g_tileFlag[NTILE];
__device__ float g_candV[(size_t)Bsz * NTILE * TCAND];
__device__ int   g_candI[(size_t)Bsz * NTILE * TCAND];
__device__ int   g_winI[Bsz * WCAP];
__device__ int   g_topIdx[Bsz * KTOP];
__device__ float g_q[Bsz * Dm];
__device__ float g_k[Bsz * KTOP * Dm];
__device__ float g_v[Bsz * KTOP * Dm];
__device__ float g_wqT[Dm * Dm];
__device__ float g_wkT[Dm * Dm];
__device__ float g_wvT[Dm * Dm];
__device__ float g_woT[Dm * Dm];
__device__ __nv_bfloat16 g_Abf[Bsz * Dm];

// ---------------- helpers ----------------
__device__ __forceinline__ uint32_t smem_u32(const void* p) {
    uint32_t a;
    asm("{ .reg .u64 t; cvta.to.shared.u64 t, %1; cvt.u32.u64 %0, t; }" : "=r"(a) : "l"(p));
    return a;
}
__device__ __forceinline__ void cp16(uint32_t saddr, const void* gaddr) {
    asm volatile("cp.async.cg.shared.global [%0], [%1], 16;\n" :: "r"(saddr), "l"(gaddr));
}
__device__ __forceinline__ void ldsm4(uint32_t& r0, uint32_t& r1, uint32_t& r2, uint32_t& r3,
                                      uint32_t addr) {
    asm volatile("ldmatrix.sync.aligned.m8n8.x4.shared.b16 {%0,%1,%2,%3}, [%4];\n"
                 : "=r"(r0), "=r"(r1), "=r"(r2), "=r"(r3) : "r"(addr));
}
__device__ __forceinline__ void mma16816(float& d0, float& d1, float& d2, float& d3,
                                         uint32_t a0, uint32_t a1, uint32_t a2, uint32_t a3,
                                         uint32_t b0, uint32_t b1) {
    asm volatile("mma.sync.aligned.m16n8k16.row.col.f32.bf16.bf16.f32 "
                 "{%0,%1,%2,%3},{%4,%5,%6,%7},{%8,%9},{%0,%1,%2,%3};\n"
                 : "+f"(d0), "+f"(d1), "+f"(d2), "+f"(d3)
                 : "r"(a0), "r"(a1), "r"(a2), "r"(a3), "r"(b0), "r"(b1));
}
#define SW128(x) ((x) ^ (((x) >> 3) & 0x70))
__device__ __forceinline__ uint32_t f2key(float f) {
    uint32_t u = __float_as_uint(f);
    return (u & 0x80000000u) ? ~u : (u | 0x80000000u);
}

// ---------------- prep: transpose weights + convert content to bf16 ----------------
__global__ void prep_kernel(const float* __restrict__ in_w,
                            const float* __restrict__ out_w,
                            const float* __restrict__ content)
{
    int idx = blockIdx.x * blockDim.x + threadIdx.x; // 65536 threads
    int d = idx >> 8;
    int e = idx & 255;
    g_wqT[e * Dm + d] = in_w[(size_t)d * Dm + e];
    g_wkT[e * Dm + d] = in_w[(size_t)(Dm + d) * Dm + e];
    g_wvT[e * Dm + d] = in_w[(size_t)(2 * Dm + d) * Dm + e];
    g_woT[e * Dm + d] = out_w[(size_t)d * Dm + e];
    g_Abf[idx] = __float2bfloat16(content[idx]);
}

// ---------------- zero the per-tile ready flags (graph-replay safe) ----------------
__global__ __launch_bounds__(256) void zero_flags_kernel()
{
    int i = blockIdx.x * 256 + threadIdx.x;
    if (i < NTILE) g_tileFlag[i] = 0;
}

// ---------------- fused: holo fp32->bf16 conversion overlapped with sims GEMM ----------------
// Grid: 4*NTILE CTAs, dispatch order per tile g: [prep half0, prep half1, sims m0, sims m1].
// Prep CTAs have strictly smaller block index than the sims CTAs that consume their
// output, so in-order dispatch guarantees forward progress (no deadlock).
__global__ __launch_bounds__(256, 2) void fused_prep_sims_kernel(
    const float* __restrict__ holo,
    const float* __restrict__ strengths)
{
    extern __shared__ char sm[];
    const uint32_t smu = smem_u32(sm);

    const int tid  = threadIdx.x;
    const int g    = blockIdx.x >> 2;      // tile id
    const int role = blockIdx.x & 3;       // 0,1 = prep halves; 2,3 = sims m-halves

    if (role < 2) {
        // ---------------- prep: convert 64 holo rows fp32 -> bf16 ----------------
        const size_t f0 = ((size_t)g * BN3 + role * 64) * Dm;   // flat float index base
        #pragma unroll
        for (int j = 0; j < 8; j++) {
            size_t e = f0 + (size_t)j * 2048 + (size_t)tid * 8;
            uint4 w;
            if (e < (size_t)CAP * Dm) {
                float4 a0 = *(const float4*)(holo + e);
                float4 a1 = *(const float4*)(holo + e + 4);
                __nv_bfloat162 p0 = __float22bfloat162_rn(make_float2(a0.x, a0.y));
                __nv_bfloat162 p1 = __float22bfloat162_rn(make_float2(a0.z, a0.w));
                __nv_bfloat162 p2 = __float22bfloat162_rn(make_float2(a1.x, a1.y));
                __nv_bfloat162 p3 = __float22bfloat162_rn(make_float2(a1.z, a1.w));
                w.x = *(uint32_t*)&p0; w.y = *(uint32_t*)&p1;
                w.z = *(uint32_t*)&p2; w.w = *(uint32_t*)&p3;
            } else {
                w = make_uint4(0u, 0u, 0u, 0u);
            }
            *(uint4*)(g_holoBf + e) = w;
        }
        __syncthreads();
        __threadfence();                       // data visible at gpu scope before flag
        if (tid == 0) atomicAdd(&g_tileFlag[g], 1);
        return;
    }

    // ---------------- sims: wait for this tile's bf16 data ----------------
    if (tid == 0) {
        volatile int* f = &g_tileFlag[g];
        while (*f < 2) __nanosleep(64);
    }
    __syncthreads();
    __threadfence();                           // acquire: order flag read before data reads

    const int lane = tid & 31;
    const int warp = tid >> 5;
    const int wm = warp >> 2;        // 0..1
    const int wn = warp & 3;         // 0..3
    const int m0 = (role - 2) * 128;
    const int n0 = g * BN3;
    const int tileIdx = g;

    float acc[4][4][4];
    #pragma unroll
    for (int a = 0; a < 4; a++)
        #pragma unroll
        for (int b = 0; b < 4; b++)
            #pragma unroll
            for (int q = 0; q < 4; q++) acc[a][b][q] = 0.f;

    auto loadChunk = [&](int kc) {
        const int buf = kc % NSTG;
        const uint32_t sb = smu + buf * STG_BYTES;
        #pragma unroll
        for (int o = 0; o < 4; o++) {
            int e = o * 256 + tid;      // 0..1023
            int r = e >> 3, seg = e & 7;
            uint32_t sw = SW128((uint32_t)(r * 128 + seg * 16));
            cp16(sb + sw, g_Abf + (size_t)(m0 + r) * Dm + kc * 64 + seg * 8);
        }
        #pragma unroll
        for (int o = 0; o < 4; o++) {
            int e = o * 256 + tid;
            int r = e >> 3, seg = e & 7;
            uint32_t sw = SW128((uint32_t)(r * 128 + seg * 16));
            cp16(sb + 16384 + sw, g_holoBf + (size_t)(n0 + r) * Dm + kc * 64 + seg * 8);
        }
    };

    loadChunk(0); asm volatile("cp.async.commit_group;\n");
    loadChunk(1); asm volatile("cp.async.commit_group;\n");
    loadChunk(2); asm volatile("cp.async.commit_group;\n");

    #pragma unroll 1
    for (int kc = 0; kc < NCHK; kc++) {
        const int buf = kc % NSTG;
        const uint32_t aBase = smu + buf * STG_BYTES;
        const uint32_t bBase = aBase + 16384;
        asm volatile("cp.async.wait_group %0;\n" :: "n"(NSTG - 1));
        __syncthreads();

        #pragma unroll
        for (int k16 = 0; k16 < 4; k16++) {
            uint32_t bfr[4][2];
            #pragma unroll
            for (int p = 0; p < 2; p++) {
                int n    = p * 16 + ((lane >> 4) << 3) + (lane & 7);
                int kcol = k16 * 16 + (((lane >> 3) & 1) << 3);
                uint32_t byte = (uint32_t)((wn * 32 + n) * 128 + kcol * 2);
                ldsm4(bfr[p * 2][0], bfr[p * 2][1], bfr[p * 2 + 1][0], bfr[p * 2 + 1][1],
                      bBase + SW128(byte));
            }
            uint32_t afr[4][4];
            #pragma unroll
            for (int mf = 0; mf < 4; mf++) {
                int r    = wm * 64 + mf * 16 + (((lane >> 3) & 1) << 3) + (lane & 7);
                int kcol = k16 * 16 + ((lane >> 4) << 3);
                uint32_t byte = (uint32_t)(r * 128 + kcol * 2);
                ldsm4(afr[mf][0], afr[mf][1], afr[mf][2], afr[mf][3], aBase + SW128(byte));
            }
            #pragma unroll
            for (int mf = 0; mf < 4; mf++)
                #pragma unroll
                for (int nf = 0; nf < 4; nf++)
                    mma16816(acc[mf][nf][0], acc[mf][nf][1], acc[mf][nf][2], acc[mf][nf][3],
                             afr[mf][0], afr[mf][1], afr[mf][2], afr[mf][3],
                             bfr[nf][0], bfr[nf][1]);
        }
        __syncthreads();
        if (kc + NSTG < NCHK) loadChunk(kc + NSTG);
        asm volatile("cp.async.commit_group;\n");
    }

    // ---------------- epilogue: per-row top-4 ----------------
    float* Ds   = (float*)(sm + OFF_DS);
    float* sLv  = (float*)(sm + OFF_LV);
    int*   sLi  = (int*)(sm + OFF_LI);
    float* sStr = (float*)(sm + OFF_STR);

    if (tid < BN3) {
        int gc = n0 + tid;
        sStr[tid] = (gc < CAP) ? strengths[gc] : 0.f;
    }

    #pragma unroll
    for (int mf = 0; mf < 4; mf++)
        #pragma unroll
        for (int nf = 0; nf < 4; nf++) {
            int r = wm * 64 + mf * 16 + (lane >> 2);
            int c = wn * 32 + nf * 8 + (lane & 3) * 2;
            *(float2*)(Ds + r * 132 + c)       = make_float2(acc[mf][nf][0], acc[mf][nf][1]);
            *(float2*)(Ds + (r + 8) * 132 + c) = make_float2(acc[mf][nf][2], acc[mf][nf][3]);
        }
    __syncthreads();

    // 2 threads per row scan 64 cols each, keep top-4
    {
        int r = tid >> 1, hc = tid & 1;
        float v[TCAND]; int id[TCAND];
        #pragma unroll
        for (int t = 0; t < TCAND; t++) { v[t] = -INFINITY; id[t] = 0x7fffffff; }
        const float* row = Ds + r * 132 + hc * 64;
        int cb = hc * 64;
        #pragma unroll 4
        for (int j = 0; j < 64; j++) {
            int c = cb + j;
            int gc = n0 + c;
            float val = row[j] * sStr[c];
            if (gc < CAP && val > v[TCAND - 1]) {     // strict >: ascending col keeps lowest idx
                v[TCAND - 1] = val; id[TCAND - 1] = gc;
                #pragma unroll
                for (int p = TCAND - 1; p > 0; p--) {
                    if (v[p] > v[p - 1]) {
                        float tv = v[p]; v[p] = v[p - 1]; v[p - 1] = tv;
                        int ti = id[p]; id[p] = id[p - 1]; id[p - 1] = ti;
                    }
                }
            }
        }
        #pragma unroll
        for (int t = 0; t < TCAND; t++) { sLv[tid * TCAND + t] = v[t]; sLi[tid * TCAND + t] = id[t]; }
    }
    __syncthreads();

    if (tid < 128) {
        const float* va = sLv + (2 * tid) * TCAND;
        const int*   ia = sLi + (2 * tid) * TCAND;
        const float* vb = sLv + (2 * tid + 1) * TCAND;
        const int*   ib = sLi + (2 * tid + 1) * TCAND;
        float mv[TCAND]; int mi[TCAND];
        int pa = 0, pb = 0;
        #pragma unroll
        for (int t = 0; t < TCAND; t++) {
            bool takeA = (va[pa] >= vb[pb]);   // A = lower cols -> lower idx on tie
            mv[t] = takeA ? va[pa] : vb[pb];
            mi[t] = takeA ? ia[pa] : ib[pb];
            if (takeA) pa++; else pb++;
        }
        size_t base = ((size_t)(m0 + tid) * NTILE + tileIdx) * TCAND;
        *(float4*)(g_candV + base) = make_float4(mv[0], mv[1], mv[2], mv[3]);
        *(int4*)(g_candI + base)   = make_int4(mi[0], mi[1], mi[2], mi[3]);
    }
}

// ---------------- merge: 3-pass radix-select threshold + compaction ----------------
__global__ __launch_bounds__(256) void select_topk_kernel()
{
    __shared__ uint32_t hist[256];
    __shared__ uint32_t sPrefix;
    __shared__ uint32_t sR;
    __shared__ int      sCount;

    const int row = blockIdx.x;
    const int tid = threadIdx.x;
    const size_t base = (size_t)row * TOTC;

    if (tid == 0) { sPrefix = 0u; sR = SELR; sCount = 0; }
    if (tid < WCAP) g_winI[row * WCAP + tid] = 0x7fffffff;

    #pragma unroll 1
    for (int shift = 24; shift >= 8; shift -= 8) {     // 3 passes (24-bit threshold)
        hist[tid] = 0u;
        __syncthreads();
        const uint32_t maskFixed = (shift == 24) ? 0u : (0xFFFFFFFFu << (shift + 8));
        const uint32_t prefix = sPrefix;
        for (int i = tid; i < TOTC; i += 256) {
            uint32_t key = f2key(g_candV[base + i]);
            if ((key & maskFixed) == prefix)
                atomicAdd(&hist[(key >> shift) & 255u], 1u);
        }
        __syncthreads();

        if (tid < 32) {
            uint32_t h[8];
            uint32_t s = 0;
            #pragma unroll
            for (int j = 0; j < 8; j++) { h[j] = hist[255 - tid * 8 - j]; s += h[j]; }
            uint32_t pre = s;
            #pragma unroll
            for (int o = 1; o < 32; o <<= 1) {
                uint32_t t2 = __shfl_up_sync(0xffffffffu, pre, o);
                if (tid >= o) pre += t2;
            }
            pre -= s;
            const uint32_t R = sR;
            if (pre < R && pre + s >= R) {
                uint32_t cum = pre;
                #pragma unroll
                for (int j = 0; j < 8; j++) {
                    int b = 255 - tid * 8 - j;
                    if (cum + h[j] >= R) {
                        sPrefix = prefix | ((uint32_t)b << shift);
                        sR = R - cum;
                        break;
                    }
                    cum += h[j];
                }
            }
        }
        __syncthreads();
    }

    const uint32_t T = sPrefix;
    for (int i = tid; i < TOTC; i += 256) {
        uint32_t key = f2key(g_candV[base + i]);
        if (key >= T) {
            int slot = atomicAdd(&sCount, 1);
            if (slot < WCAP) g_winI[row * WCAP + slot] = g_candI[base + i];
        }
    }
}

// ---------------- rescore window exactly in fp32, pick top-10 ----------------
__global__ __launch_bounds__(256) void rescore_kernel(
    const float* __restrict__ content,
    const float* __restrict__ holo,
    const float* __restrict__ strengths)
{
    __shared__ float cont[Dm];
    __shared__ float sv[WCAP];
    __shared__ int   sid[WCAP];

    const int b = blockIdx.x;
    const int tid = threadIdx.x;
    const int lane = tid & 31, warp = tid >> 5;

    cont[tid] = content[(size_t)b * Dm + tid];
    __syncthreads();

    for (int c = warp; c < WCAP; c += 8) {
        int idx = g_winI[b * WCAP + c];
        float part = 0.f;
        if (idx < CAP) {
            const float* hp = holo + (size_t)idx * Dm + lane * 8;
            const float* cp = cont + lane * 8;
            float4 h0 = *(const float4*)hp;
            float4 h1 = *(const float4*)(hp + 4);
            part = h0.x * cp[0] + h0.y * cp[1] + h0.z * cp[2] + h0.w * cp[3]
                 + h1.x * cp[4] + h1.y * cp[5] + h1.z * cp[6] + h1.w * cp[7];
        }
        #pragma unroll
        for (int s = 16; s >= 1; s >>= 1) part += __shfl_xor_sync(0xffffffffu, part, s);
        if (lane == 0) {
            sv[c]  = (idx < CAP) ? part * strengths[idx] : -INFINITY;
            sid[c] = idx;
        }
    }
    __syncthreads();

    if (tid == 0) {
        float w[KTOP]; int wi[KTOP];
        #pragma unroll
        for (int t = 0; t < KTOP; t++) { w[t] = -INFINITY; wi[t] = 0x7fffffff; }
        for (int e = 0; e < WCAP; e++) {
            float nv = sv[e]; int ni = sid[e];
            if (nv > w[KTOP - 1] || (nv == w[KTOP - 1] && ni < wi[KTOP - 1])) {
                w[KTOP - 1] = nv; wi[KTOP - 1] = ni;
                #pragma unroll
                for (int p = KTOP - 1; p > 0; p--) {
                    if (w[p] > w[p - 1] || (w[p] == w[p - 1] && wi[p] < wi[p - 1])) {
                        float tv = w[p]; w[p] = w[p - 1]; w[p - 1] = tv;
                        int ti = wi[p]; wi[p] = wi[p - 1]; wi[p - 1] = ti;
                    }
                }
            }
        }
        for (int t = 0; t < KTOP; t++) g_topIdx[b * KTOP + t] = wi[t];
    }
}

// ---------------- pass 3a: q projection (2 rows / block) ----------------
__global__ __launch_bounds__(256) void proj_q_kernel(
    const float* __restrict__ content, const float* __restrict__ in_b)
{
    __shared__ float rows[2][Dm];
    const int blk = blockIdx.x;
    const int tid = threadIdx.x;
    for (int i = tid; i < 2 * Dm; i += 256)
        rows[i >> 8][i & 255] = content[(size_t)blk * 2 * Dm + i];
    __syncthreads();

    float a0 = 0.f, a1 = 0.f;
    const int d = tid;
    #pragma unroll 4
    for (int e = 0; e < Dm; e++) {
        float w = g_wqT[e * Dm + d];
        a0 = fmaf(rows[0][e], w, a0);
        a1 = fmaf(rows[1][e], w, a1);
    }
    float bq = in_b[d];
    g_q[(size_t)(blk * 2 + 0) * Dm + d] = a0 + bq;
    g_q[(size_t)(blk * 2 + 1) * Dm + d] = a1 + bq;
}

// ---------------- pass 3b: gather + k/v projections ----------------
__global__ __launch_bounds__(256) void proj_kv_kernel(
    const float* __restrict__ holo, const float* __restrict__ in_b)
{
    __shared__ float rows[16][Dm];
    const int blk = blockIdx.x;
    const int tid = threadIdx.x;
    for (int i = tid; i < 16 * Dm; i += 256) {
        int r = i >> 8;
        int c = i & 255;
        int hid = g_topIdx[blk * 16 + r];
        rows[r][c] = holo[(size_t)hid * Dm + c];
    }
    __syncthreads();

    float ka[16], va[16];
    #pragma unroll
    for (int j = 0; j < 16; j++) { ka[j] = 0.f; va[j] = 0.f; }
    const int d = tid;
    for (int e = 0; e < Dm; e++) {
        float wk = g_wkT[e * Dm + d];
        float wv = g_wvT[e * Dm + d];
        #pragma unroll
        for (int j = 0; j < 16; j++) {
            float rv = rows[j][e];
            ka[j] = fmaf(rv, wk, ka[j]);
            va[j] = fmaf(rv, wv, va[j]);
        }
    }
    float bk = in_b[Dm + d];
    float bv2 = in_b[2 * Dm + d];
    #pragma unroll
    for (int j = 0; j < 16; j++) {
        int g = blk * 16 + j;
        g_k[(size_t)g * Dm + d] = ka[j] + bk;
        g_v[(size_t)g * Dm + d] = va[j] + bv2;
    }
}

// ---------------- pass 3c: attention + out projection + attn_weights ----------------
__global__ __launch_bounds__(256) void attn_kernel(
    const float* __restrict__ out_b, float* __restrict__ out)
{
    __shared__ float qs[Dm];
    __shared__ float ks[KTOP][Dm];
    __shared__ float vs[KTOP][Dm];
    __shared__ float attnS[Hh][KTOP];
    __shared__ float ctxS[Dm];

    const int b = blockIdx.x;
    const int tid = threadIdx.x;

    qs[tid] = g_q[(size_t)b * Dm + tid];
    for (int i = tid; i < KTOP * Dm; i += 256) {
        int kk = i >> 8;
        int c = i & 255;
        ks[kk][c] = g_k[((size_t)b * KTOP + kk) * Dm + c];
        vs[kk][c] = g_v[((size_t)b * KTOP + kk) * Dm + c];
    }
    __syncthreads();

    if (tid < Hh * KTOP) {
        int h = tid / KTOP, kk = tid % KTOP;
        float s = 0.f;
        #pragma unroll
        for (int d2 = 0; d2 < HD; d2++)
            s = fmaf(qs[h * HD + d2], ks[kk][h * HD + d2], s);
        attnS[h][kk] = s * 0.17677669529663687f;  // 1/sqrt(32)
    }
    __syncthreads();

    if (tid < Hh) {
        int h = tid;
        float mx = -INFINITY;
        for (int kk = 0; kk < KTOP; kk++) mx = fmaxf(mx, attnS[h][kk]);
        float sum = 0.f;
        for (int kk = 0; kk < KTOP; kk++) {
            float e2 = expf(attnS[h][kk] - mx);
            attnS[h][kk] = e2;
            sum += e2;
        }
        float inv = 1.f / sum;
        for (int kk = 0; kk < KTOP; kk++) attnS[h][kk] *= inv;
    }
    __syncthreads();

    if (tid < KTOP) {
        float m = 0.f;
        for (int h = 0; h < Hh; h++) m += attnS[h][tid];
        out[(size_t)Bsz * Dm + (size_t)b * KTOP + tid] = m * 0.125f;
    }

    {
        int d2 = tid, h = d2 >> 5;
        float c = 0.f;
        #pragma unroll
        for (int kk = 0; kk < KTOP; kk++)
            c = fmaf(attnS[h][kk], vs[kk][d2], c);
        ctxS[d2] = c;
    }
    __syncthreads();

    float r = 0.f;
    for (int e = 0; e < Dm; e++)
        r = fmaf(ctxS[e], g_woT[e * Dm + tid], r);
    out[(size_t)b * Dm + tid] = r + out_b[tid];
}

// ---------------- launch ----------------
extern "C" void kernel_launch(void* const* d_in, const int* in_sizes, int n_in,
                              void* d_out, int out_size)
{
    const float* content   = (const float*)d_in[0];
    const float* hologram  = (const float*)d_in[1];
    const float* strengths = (const float*)d_in[2];
    const float* in_w      = (const float*)d_in[3];
    const float* in_b      = (const float*)d_in[4];
    const float* out_w     = (const float*)d_in[5];
    const float* out_b     = (const float*)d_in[6];
    float* out = (float*)d_out;

    cudaFuncSetAttribute(fused_prep_sims_kernel,
                         cudaFuncAttributeMaxDynamicSharedMemorySize, SMEM3);

    prep_kernel<<<256, 256>>>(in_w, out_w, content);
    zero_flags_kernel<<<(NTILE + 255) / 256, 256>>>();

    fused_prep_sims_kernel<<<4 * NTILE, 256, SMEM3>>>(hologram, strengths);

    select_topk_kernel<<<Bsz, 256>>>();

    rescore_kernel<<<Bsz, 256>>>(content, hologram, strengths);

    proj_q_kernel<<<Bsz / 2, 256>>>(content, in_b);
    proj_kv_kernel<<<(Bsz * KTOP) / 16, 256>>>(hologram, in_b);
    attn_kernel<<<Bsz, 256>>>(out_b, out);
}

// round 16
// speedup vs baseline: 1.0766x; 1.0766x over previous
#include <cuda_runtime.h>
#include <cuda_bf16.h>
#include <math.h>
#include <stdint.h>

#define Bsz   256
#define Dm    256
#define Hh    8
#define HD    32
#define KTOP  10
#define CAP   500000

#define BN3    128           // holo rows per CTA
#define NTILE  3907          // ceil(500000/128)
#define PADROWS ((size_t)NTILE * BN3)   // 500096
#define TCAND  4             // per-tile candidates kept per row
#define NCHK   4             // K chunks of 64
#define NSTG   3

#define TOTC   (NTILE * TCAND)          // 15628 candidates per row
#define SELR   24                       // radix-select rank
#define WCAP   48                       // rescore window capacity

#define PREPW_BLOCKS 256                // weight/content blocks in merged prep grid

// ---- sims kernel dynamic smem (bytes): 3 stages x (A 16KB + B 16KB) ----
#define STG_BYTES 32768
#define SMEM3     98304
// epilogue overlay
#define OFF_DS    0          // float [128][132] = 67584
#define OFF_LV    67584      // float [256][4]   = 4096
#define OFF_LI    71680      // int   [256][4]   = 4096
#define OFF_STR   75776      // float [128]

#define SEL_SMEM  (TOTC * 4)            // 62512 bytes of cached keys

// ---------------- device scratch ----------------
__device__ __nv_bfloat16 g_holoBf[PADROWS * Dm];
__device__ float g_candV[(size_t)Bsz * NTILE * TCAND];
__device__ int   g_candI[(size_t)Bsz * NTILE * TCAND];
__device__ int   g_winI[Bsz * WCAP];
__device__ int   g_topIdx[Bsz * KTOP];
__device__ float g_q[Bsz * Dm];
__device__ float g_k[Bsz * KTOP * Dm];
__device__ float g_v[Bsz * KTOP * Dm];
__device__ float g_wqT[Dm * Dm];
__device__ float g_wkT[Dm * Dm];
__device__ float g_wvT[Dm * Dm];
__device__ float g_woT[Dm * Dm];
__device__ __nv_bfloat16 g_Abf[Bsz * Dm];

// ---------------- helpers ----------------
__device__ __forceinline__ uint32_t smem_u32(const void* p) {
    uint32_t a;
    asm("{ .reg .u64 t; cvta.to.shared.u64 t, %1; cvt.u32.u64 %0, t; }" : "=r"(a) : "l"(p));
    return a;
}
__device__ __forceinline__ void cp16(uint32_t saddr, const void* gaddr) {
    asm volatile("cp.async.cg.shared.global [%0], [%1], 16;\n" :: "r"(saddr), "l"(gaddr));
}
__device__ __forceinline__ void ldsm4(uint32_t& r0, uint32_t& r1, uint32_t& r2, uint32_t& r3,
                                      uint32_t addr) {
    asm volatile("ldmatrix.sync.aligned.m8n8.x4.shared.b16 {%0,%1,%2,%3}, [%4];\n"
                 : "=r"(r0), "=r"(r1), "=r"(r2), "=r"(r3) : "r"(addr));
}
__device__ __forceinline__ void mma16816(float& d0, float& d1, float& d2, float& d3,
                                         uint32_t a0, uint32_t a1, uint32_t a2, uint32_t a3,
                                         uint32_t b0, uint32_t b1) {
    asm volatile("mma.sync.aligned.m16n8k16.row.col.f32.bf16.bf16.f32 "
                 "{%0,%1,%2,%3},{%4,%5,%6,%7},{%8,%9},{%0,%1,%2,%3};\n"
                 : "+f"(d0), "+f"(d1), "+f"(d2), "+f"(d3)
                 : "r"(a0), "r"(a1), "r"(a2), "r"(a3), "r"(b0), "r"(b1));
}
#define SW128(x) ((x) ^ (((x) >> 3) & 0x70))
__device__ __forceinline__ uint32_t f2key(float f) {
    uint32_t u = __float_as_uint(f);
    return (u & 0x80000000u) ? ~u : (u | 0x80000000u);
}

// ---------------- merged prep: weights/content + hologram fp32 -> bf16 ----------------
// blocks [0, PREPW_BLOCKS): transpose weights + convert content (65536 elems)
// blocks [PREPW_BLOCKS, ...): convert hologram (8 floats / thread), zero padded
__global__ __launch_bounds__(256) void prep_all_kernel(
    const float* __restrict__ in_w,
    const float* __restrict__ out_w,
    const float* __restrict__ content,
    const float* __restrict__ holo)
{
    if (blockIdx.x < PREPW_BLOCKS) {
        int idx = blockIdx.x * 256 + threadIdx.x;   // 0..65535
        int d = idx >> 8;
        int e = idx & 255;
        g_wqT[e * Dm + d] = in_w[(size_t)d * Dm + e];
        g_wkT[e * Dm + d] = in_w[(size_t)(Dm + d) * Dm + e];
        g_wvT[e * Dm + d] = in_w[(size_t)(2 * Dm + d) * Dm + e];
        g_woT[e * Dm + d] = out_w[(size_t)d * Dm + e];
        g_Abf[idx] = __float2bfloat16(content[idx]);
        return;
    }
    size_t g = (size_t)(blockIdx.x - PREPW_BLOCKS) * 256 + threadIdx.x;
    size_t e = g * 8;
    if (e >= PADROWS * Dm) return;
    uint4 w;
    if (e < (size_t)CAP * Dm) {
        float4 f0 = *(const float4*)(holo + e);
        float4 f1 = *(const float4*)(holo + e + 4);
        __nv_bfloat162 p0 = __float22bfloat162_rn(make_float2(f0.x, f0.y));
        __nv_bfloat162 p1 = __float22bfloat162_rn(make_float2(f0.z, f0.w));
        __nv_bfloat162 p2 = __float22bfloat162_rn(make_float2(f1.x, f1.y));
        __nv_bfloat162 p3 = __float22bfloat162_rn(make_float2(f1.z, f1.w));
        w.x = *(uint32_t*)&p0; w.y = *(uint32_t*)&p1;
        w.z = *(uint32_t*)&p2; w.w = *(uint32_t*)&p3;
    } else {
        w = make_uint4(0u, 0u, 0u, 0u);
    }
    *(uint4*)(g_holoBf + e) = w;
}

// ---------------- pass 1: bf16 mma.sync sims GEMM + per-tile top-4 ----------------
// grid (2, NTILE): x = 128-row content half (m-half pairs adjacent in schedule
// so the second half's holo tile hits L2), y = 128-col holo tile.
__global__ __launch_bounds__(256, 2) void sims_mma_kernel(
    const float* __restrict__ strengths)
{
    extern __shared__ char sm[];
    const uint32_t smu = smem_u32(sm);

    const int tid  = threadIdx.x;
    const int lane = tid & 31;
    const int warp = tid >> 5;
    const int wm = warp >> 2;        // 0..1
    const int wn = warp & 3;         // 0..3
    const int m0 = blockIdx.x * 128;
    const int n0 = blockIdx.y * BN3;
    const int tileIdx = blockIdx.y;

    float acc[4][4][4];
    #pragma unroll
    for (int a = 0; a < 4; a++)
        #pragma unroll
        for (int b = 0; b < 4; b++)
            #pragma unroll
            for (int q = 0; q < 4; q++) acc[a][b][q] = 0.f;

    auto loadChunk = [&](int kc) {
        const int buf = kc % NSTG;
        const uint32_t sb = smu + buf * STG_BYTES;
        #pragma unroll
        for (int o = 0; o < 4; o++) {
            int e = o * 256 + tid;      // 0..1023
            int r = e >> 3, seg = e & 7;
            uint32_t sw = SW128((uint32_t)(r * 128 + seg * 16));
            cp16(sb + sw, g_Abf + (size_t)(m0 + r) * Dm + kc * 64 + seg * 8);
        }
        #pragma unroll
        for (int o = 0; o < 4; o++) {
            int e = o * 256 + tid;
            int r = e >> 3, seg = e & 7;
            uint32_t sw = SW128((uint32_t)(r * 128 + seg * 16));
            cp16(sb + 16384 + sw, g_holoBf + (size_t)(n0 + r) * Dm + kc * 64 + seg * 8);
        }
    };

    loadChunk(0); asm volatile("cp.async.commit_group;\n");
    loadChunk(1); asm volatile("cp.async.commit_group;\n");
    loadChunk(2); asm volatile("cp.async.commit_group;\n");

    #pragma unroll 1
    for (int kc = 0; kc < NCHK; kc++) {
        const int buf = kc % NSTG;
        const uint32_t aBase = smu + buf * STG_BYTES;
        const uint32_t bBase = aBase + 16384;
        asm volatile("cp.async.wait_group %0;\n" :: "n"(NSTG - 1));
        __syncthreads();

        #pragma unroll
        for (int k16 = 0; k16 < 4; k16++) {
            uint32_t bfr[4][2];
            #pragma unroll
            for (int p = 0; p < 2; p++) {
                int n    = p * 16 + ((lane >> 4) << 3) + (lane & 7);
                int kcol = k16 * 16 + (((lane >> 3) & 1) << 3);
                uint32_t byte = (uint32_t)((wn * 32 + n) * 128 + kcol * 2);
                ldsm4(bfr[p * 2][0], bfr[p * 2][1], bfr[p * 2 + 1][0], bfr[p * 2 + 1][1],
                      bBase + SW128(byte));
            }
            uint32_t afr[4][4];
            #pragma unroll
            for (int mf = 0; mf < 4; mf++) {
                int r    = wm * 64 + mf * 16 + (((lane >> 3) & 1) << 3) + (lane & 7);
                int kcol = k16 * 16 + ((lane >> 4) << 3);
                uint32_t byte = (uint32_t)(r * 128 + kcol * 2);
                ldsm4(afr[mf][0], afr[mf][1], afr[mf][2], afr[mf][3], aBase + SW128(byte));
            }
            #pragma unroll
            for (int mf = 0; mf < 4; mf++)
                #pragma unroll
                for (int nf = 0; nf < 4; nf++)
                    mma16816(acc[mf][nf][0], acc[mf][nf][1], acc[mf][nf][2], acc[mf][nf][3],
                             afr[mf][0], afr[mf][1], afr[mf][2], afr[mf][3],
                             bfr[nf][0], bfr[nf][1]);
        }
        __syncthreads();
        if (kc + NSTG < NCHK) loadChunk(kc + NSTG);
        asm volatile("cp.async.commit_group;\n");
    }

    // ---------------- epilogue: per-row top-4 ----------------
    float* Ds   = (float*)(sm + OFF_DS);
    float* sLv  = (float*)(sm + OFF_LV);
    int*   sLi  = (int*)(sm + OFF_LI);
    float* sStr = (float*)(sm + OFF_STR);

    if (tid < BN3) {
        int gc = n0 + tid;
        sStr[tid] = (gc < CAP) ? strengths[gc] : 0.f;
    }

    #pragma unroll
    for (int mf = 0; mf < 4; mf++)
        #pragma unroll
        for (int nf = 0; nf < 4; nf++) {
            int r = wm * 64 + mf * 16 + (lane >> 2);
            int c = wn * 32 + nf * 8 + (lane & 3) * 2;
            *(float2*)(Ds + r * 132 + c)       = make_float2(acc[mf][nf][0], acc[mf][nf][1]);
            *(float2*)(Ds + (r + 8) * 132 + c) = make_float2(acc[mf][nf][2], acc[mf][nf][3]);
        }
    __syncthreads();

    // 2 threads per row scan 64 cols each, keep top-4
    {
        int r = tid >> 1, hc = tid & 1;
        float v[TCAND]; int id[TCAND];
        #pragma unroll
        for (int t = 0; t < TCAND; t++) { v[t] = -INFINITY; id[t] = 0x7fffffff; }
        const float* row = Ds + r * 132 + hc * 64;
        int cb = hc * 64;
        #pragma unroll 4
        for (int j = 0; j < 64; j++) {
            int c = cb + j;
            int gc = n0 + c;
            float val = row[j] * sStr[c];
            if (gc < CAP && val > v[TCAND - 1]) {     // strict >: ascending col keeps lowest idx
                v[TCAND - 1] = val; id[TCAND - 1] = gc;
                #pragma unroll
                for (int p = TCAND - 1; p > 0; p--) {
                    if (v[p] > v[p - 1]) {
                        float tv = v[p]; v[p] = v[p - 1]; v[p - 1] = tv;
                        int ti = id[p]; id[p] = id[p - 1]; id[p - 1] = ti;
                    }
                }
            }
        }
        #pragma unroll
        for (int t = 0; t < TCAND; t++) { sLv[tid * TCAND + t] = v[t]; sLi[tid * TCAND + t] = id[t]; }
    }
    __syncthreads();

    if (tid < 128) {
        const float* va = sLv + (2 * tid) * TCAND;
        const int*   ia = sLi + (2 * tid) * TCAND;
        const float* vb = sLv + (2 * tid + 1) * TCAND;
        const int*   ib = sLi + (2 * tid + 1) * TCAND;
        float mv[TCAND]; int mi[TCAND];
        int pa = 0, pb = 0;
        #pragma unroll
        for (int t = 0; t < TCAND; t++) {
            bool takeA = (va[pa] >= vb[pb]);   // A = lower cols -> lower idx on tie
            mv[t] = takeA ? va[pa] : vb[pb];
            mi[t] = takeA ? ia[pa] : ib[pb];
            if (takeA) pa++; else pb++;
        }
        size_t base = ((size_t)(m0 + tid) * NTILE + tileIdx) * TCAND;
        *(float4*)(g_candV + base) = make_float4(mv[0], mv[1], mv[2], mv[3]);
        *(int4*)(g_candI + base)   = make_int4(mi[0], mi[1], mi[2], mi[3]);
    }
}

// ---------------- merge: 3-pass radix-select with smem-cached keys ----------------
// Pass 1 loads candV once from global, caches sortable keys in smem; passes 2-3
// and the compaction read smem only (cuts global traffic 4x).
__global__ __launch_bounds__(256) void select_topk_kernel()
{
    extern __shared__ uint32_t skeys[];        // TOTC keys = 62512 bytes
    __shared__ uint32_t hist[256];
    __shared__ uint32_t sPrefix;
    __shared__ uint32_t sR;
    __shared__ int      sCount;

    const int row = blockIdx.x;
    const int tid = threadIdx.x;
    const size_t base = (size_t)row * TOTC;

    if (tid == 0) { sPrefix = 0u; sR = SELR; sCount = 0; }
    if (tid < WCAP) g_winI[row * WCAP + tid] = 0x7fffffff;
    hist[tid] = 0u;
    __syncthreads();

    // pass 1 (shift 24): global load + cache + histogram
    for (int i = tid; i < TOTC; i += 256) {
        uint32_t key = f2key(g_candV[base + i]);
        skeys[i] = key;
        atomicAdd(&hist[key >> 24], 1u);
    }
    __syncthreads();

    #pragma unroll 1
    for (int shift = 24; shift >= 8; shift -= 8) {
        // warp 0: find bin containing rank sR, scanning bins high -> low
        if (tid < 32) {
            uint32_t h[8];
            uint32_t s = 0;
            #pragma unroll
            for (int j = 0; j < 8; j++) { h[j] = hist[255 - tid * 8 - j]; s += h[j]; }
            uint32_t pre = s;
            #pragma unroll
            for (int o = 1; o < 32; o <<= 1) {
                uint32_t t2 = __shfl_up_sync(0xffffffffu, pre, o);
                if (tid >= o) pre += t2;
            }
            pre -= s;                         // exclusive prefix (counts in higher groups)
            const uint32_t R = sR;
            if (pre < R && pre + s >= R) {
                uint32_t cum = pre;
                #pragma unroll
                for (int j = 0; j < 8; j++) {
                    int b = 255 - tid * 8 - j;
                    if (cum + h[j] >= R) {
                        sPrefix = sPrefix | ((uint32_t)b << shift);
                        sR = R - cum;
                        break;
                    }
                    cum += h[j];
                }
            }
        }
        __syncthreads();

        if (shift > 8) {
            // build next histogram from smem keys
            hist[tid] = 0u;
            __syncthreads();
            const int nshift = shift - 8;
            const uint32_t maskFixed = 0xFFFFFFFFu << shift;
            const uint32_t prefix = sPrefix;
            for (int i = tid; i < TOTC; i += 256) {
                uint32_t key = skeys[i];
                if ((key & maskFixed) == prefix)
                    atomicAdd(&hist[(key >> nshift) & 255u], 1u);
            }
            __syncthreads();
        }
    }

    const uint32_t T = sPrefix;   // 24-bit-resolved threshold (<= exact 24th key)
    for (int i = tid; i < TOTC; i += 256) {
        if (skeys[i] >= T) {
            int slot = atomicAdd(&sCount, 1);
            if (slot < WCAP) g_winI[row * WCAP + slot] = g_candI[base + i];
        }
    }
}

// ---------------- rescore window exactly in fp32, pick top-10 ----------------
__global__ __launch_bounds__(256) void rescore_kernel(
    const float* __restrict__ content,
    const float* __restrict__ holo,
    const float* __restrict__ strengths)
{
    __shared__ float cont[Dm];
    __shared__ float sv[WCAP];
    __shared__ int   sid[WCAP];

    const int b = blockIdx.x;
    const int tid = threadIdx.x;
    const int lane = tid & 31, warp = tid >> 5;

    cont[tid] = content[(size_t)b * Dm + tid];
    __syncthreads();

    for (int c = warp; c < WCAP; c += 8) {
        int idx = g_winI[b * WCAP + c];
        float part = 0.f;
        if (idx < CAP) {
            const float* hp = holo + (size_t)idx * Dm + lane * 8;
            const float* cp = cont + lane * 8;
            float4 h0 = *(const float4*)hp;
            float4 h1 = *(const float4*)(hp + 4);
            part = h0.x * cp[0] + h0.y * cp[1] + h0.z * cp[2] + h0.w * cp[3]
                 + h1.x * cp[4] + h1.y * cp[5] + h1.z * cp[6] + h1.w * cp[7];
        }
        #pragma unroll
        for (int s = 16; s >= 1; s >>= 1) part += __shfl_xor_sync(0xffffffffu, part, s);
        if (lane == 0) {
            sv[c]  = (idx < CAP) ? part * strengths[idx] : -INFINITY;
            sid[c] = idx;
        }
    }
    __syncthreads();

    if (tid == 0) {
        float w[KTOP]; int wi[KTOP];
        #pragma unroll
        for (int t = 0; t < KTOP; t++) { w[t] = -INFINITY; wi[t] = 0x7fffffff; }
        for (int e = 0; e < WCAP; e++) {
            float nv = sv[e]; int ni = sid[e];
            if (nv > w[KTOP - 1] || (nv == w[KTOP - 1] && ni < wi[KTOP - 1])) {
                w[KTOP - 1] = nv; wi[KTOP - 1] = ni;
                #pragma unroll
                for (int p = KTOP - 1; p > 0; p--) {
                    if (w[p] > w[p - 1] || (w[p] == w[p - 1] && wi[p] < wi[p - 1])) {
                        float tv = w[p]; w[p] = w[p - 1]; w[p - 1] = tv;
                        int ti = wi[p]; wi[p] = wi[p - 1]; wi[p - 1] = ti;
                    }
                }
            }
        }
        for (int t = 0; t < KTOP; t++) g_topIdx[b * KTOP + t] = wi[t];
    }
}

// ---------------- pass 3a: q projection (2 rows / block) ----------------
__global__ __launch_bounds__(256) void proj_q_kernel(
    const float* __restrict__ content, const float* __restrict__ in_b)
{
    __shared__ float rows[2][Dm];
    const int blk = blockIdx.x;
    const int tid = threadIdx.x;
    for (int i = tid; i < 2 * Dm; i += 256)
        rows[i >> 8][i & 255] = content[(size_t)blk * 2 * Dm + i];
    __syncthreads();

    float a0 = 0.f, a1 = 0.f;
    const int d = tid;
    #pragma unroll 4
    for (int e = 0; e < Dm; e++) {
        float w = g_wqT[e * Dm + d];
        a0 = fmaf(rows[0][e], w, a0);
        a1 = fmaf(rows[1][e], w, a1);
    }
    float bq = in_b[d];
    g_q[(size_t)(blk * 2 + 0) * Dm + d] = a0 + bq;
    g_q[(size_t)(blk * 2 + 1) * Dm + d] = a1 + bq;
}

// ---------------- pass 3b: gather + k/v projections ----------------
__global__ __launch_bounds__(256) void proj_kv_kernel(
    const float* __restrict__ holo, const float* __restrict__ in_b)
{
    __shared__ float rows[16][Dm];
    const int blk = blockIdx.x;
    const int tid = threadIdx.x;
    for (int i = tid; i < 16 * Dm; i += 256) {
        int r = i >> 8;
        int c = i & 255;
        int hid = g_topIdx[blk * 16 + r];
        rows[r][c] = holo[(size_t)hid * Dm + c];
    }
    __syncthreads();

    float ka[16], va[16];
    #pragma unroll
    for (int j = 0; j < 16; j++) { ka[j] = 0.f; va[j] = 0.f; }
    const int d = tid;
    for (int e = 0; e < Dm; e++) {
        float wk = g_wkT[e * Dm + d];
        float wv = g_wvT[e * Dm + d];
        #pragma unroll
        for (int j = 0; j < 16; j++) {
            float rv = rows[j][e];
            ka[j] = fmaf(rv, wk, ka[j]);
            va[j] = fmaf(rv, wv, va[j]);
        }
    }
    float bk = in_b[Dm + d];
    float bv2 = in_b[2 * Dm + d];
    #pragma unroll
    for (int j = 0; j < 16; j++) {
        int g = blk * 16 + j;
        g_k[(size_t)g * Dm + d] = ka[j] + bk;
        g_v[(size_t)g * Dm + d] = va[j] + bv2;
    }
}

// ---------------- pass 3c: attention + out projection + attn_weights ----------------
__global__ __launch_bounds__(256) void attn_kernel(
    const float* __restrict__ out_b, float* __restrict__ out)
{
    __shared__ float qs[Dm];
    __shared__ float ks[KTOP][Dm];
    __shared__ float vs[KTOP][Dm];
    __shared__ float attnS[Hh][KTOP];
    __shared__ float ctxS[Dm];

    const int b = blockIdx.x;
    const int tid = threadIdx.x;

    qs[tid] = g_q[(size_t)b * Dm + tid];
    for (int i = tid; i < KTOP * Dm; i += 256) {
        int kk = i >> 8;
        int c = i & 255;
        ks[kk][c] = g_k[((size_t)b * KTOP + kk) * Dm + c];
        vs[kk][c] = g_v[((size_t)b * KTOP + kk) * Dm + c];
    }
    __syncthreads();

    if (tid < Hh * KTOP) {
        int h = tid / KTOP, kk = tid % KTOP;
        float s = 0.f;
        #pragma unroll
        for (int d2 = 0; d2 < HD; d2++)
            s = fmaf(qs[h * HD + d2], ks[kk][h * HD + d2], s);
        attnS[h][kk] = s * 0.17677669529663687f;  // 1/sqrt(32)
    }
    __syncthreads();

    if (tid < Hh) {
        int h = tid;
        float mx = -INFINITY;
        for (int kk = 0; kk < KTOP; kk++) mx = fmaxf(mx, attnS[h][kk]);
        float sum = 0.f;
        for (int kk = 0; kk < KTOP; kk++) {
            float e2 = expf(attnS[h][kk] - mx);
            attnS[h][kk] = e2;
            sum += e2;
        }
        float inv = 1.f / sum;
        for (int kk = 0; kk < KTOP; kk++) attnS[h][kk] *= inv;
    }
    __syncthreads();

    if (tid < KTOP) {
        float m = 0.f;
        for (int h = 0; h < Hh; h++) m += attnS[h][tid];
        out[(size_t)Bsz * Dm + (size_t)b * KTOP + tid] = m * 0.125f;
    }

    {
        int d2 = tid, h = d2 >> 5;
        float c = 0.f;
        #pragma unroll
        for (int kk = 0; kk < KTOP; kk++)
            c = fmaf(attnS[h][kk], vs[kk][d2], c);
        ctxS[d2] = c;
    }
    __syncthreads();

    float r = 0.f;
    for (int e = 0; e < Dm; e++)
        r = fmaf(ctxS[e], g_woT[e * Dm + tid], r);
    out[(size_t)b * Dm + tid] = r + out_b[tid];
}

// ---------------- launch ----------------
extern "C" void kernel_launch(void* const* d_in, const int* in_sizes, int n_in,
                              void* d_out, int out_size)
{
    const float* content   = (const float*)d_in[0];
    const float* hologram  = (const float*)d_in[1];
    const float* strengths = (const float*)d_in[2];
    const float* in_w      = (const float*)d_in[3];
    const float* in_b      = (const float*)d_in[4];
    const float* out_w     = (const float*)d_in[5];
    const float* out_b     = (const float*)d_in[6];
    float* out = (float*)d_out;

    cudaFuncSetAttribute(sims_mma_kernel,
                         cudaFuncAttributeMaxDynamicSharedMemorySize, SMEM3);
    cudaFuncSetAttribute(select_topk_kernel,
                         cudaFuncAttributeMaxDynamicSharedMemorySize, SEL_SMEM);

    {
        size_t nvec = PADROWS * Dm / 8;
        unsigned holoBlocks = (unsigned)((nvec + 255) / 256);
        prep_all_kernel<<<PREPW_BLOCKS + holoBlocks, 256>>>(in_w, out_w, content, hologram);
    }

    dim3 g1(2, NTILE);
    sims_mma_kernel<<<g1, 256, SMEM3>>>(strengths);

    select_topk_kernel<<<Bsz, 256, SEL_SMEM>>>();

    rescore_kernel<<<Bsz, 256>>>(content, hologram, strengths);

    proj_q_kernel<<<Bsz / 2, 256>>>(content, in_b);
    proj_kv_kernel<<<(Bsz * KTOP) / 16, 256>>>(hologram, in_b);
    attn_kernel<<<Bsz, 256>>>(out_b, out);
}

// round 17
// speedup vs baseline: 1.1723x; 1.0888x over previous
#include <cuda_runtime.h>
#include <cuda_bf16.h>
#include <math.h>
#include <stdint.h>

#define Bsz   256
#define Dm    256
#define Hh    8
#define HD    32
#define KTOP  10
#define CAP   500000

#define BN3    128           // holo rows per CTA
#define NTILE  3907          // ceil(500000/128)
#define PADROWS ((size_t)NTILE * BN3)   // 500096
#define TCAND  4             // per-tile candidates kept per row
#define NCHK   4             // K chunks of 64
#define NSTG   3

#define TOTC   (NTILE * TCAND)          // 15628 candidates per row
#define SELR   24                       // radix-select rank
#define WCAP   48                       // rescore window capacity

#define PREPW_BLOCKS 256                // weight/content blocks in merged prep grid

// ---- sims kernel dynamic smem (bytes): 3 stages x (A 16KB + B 16KB) ----
#define STG_BYTES 32768
#define SMEM3     98304
// epilogue overlay
#define OFF_DS    0          // float [128][132] = 67584
#define OFF_LV    67584      // float [256][4]   = 4096
#define OFF_LI    71680      // int   [256][4]   = 4096
#define OFF_STR   75776      // float [128]

#define SEL_SMEM  (TOTC * 4)            // 62512 bytes of cached keys

// ---------------- device scratch ----------------
__device__ __nv_bfloat16 g_holoBf[PADROWS * Dm];
__device__ float g_candV[(size_t)Bsz * NTILE * TCAND];
__device__ int   g_candI[(size_t)Bsz * NTILE * TCAND];
__device__ int   g_topIdx[Bsz * KTOP];
__device__ float g_wqT[Dm * Dm];
__device__ float g_wkT[Dm * Dm];
__device__ float g_wvT[Dm * Dm];
__device__ float g_woT[Dm * Dm];
__device__ __nv_bfloat16 g_Abf[Bsz * Dm];

// ---------------- helpers ----------------
__device__ __forceinline__ uint32_t smem_u32(const void* p) {
    uint32_t a;
    asm("{ .reg .u64 t; cvta.to.shared.u64 t, %1; cvt.u32.u64 %0, t; }" : "=r"(a) : "l"(p));
    return a;
}
__device__ __forceinline__ void cp16(uint32_t saddr, const void* gaddr) {
    asm volatile("cp.async.cg.shared.global [%0], [%1], 16;\n" :: "r"(saddr), "l"(gaddr));
}
__device__ __forceinline__ void ldsm4(uint32_t& r0, uint32_t& r1, uint32_t& r2, uint32_t& r3,
                                      uint32_t addr) {
    asm volatile("ldmatrix.sync.aligned.m8n8.x4.shared.b16 {%0,%1,%2,%3}, [%4];\n"
                 : "=r"(r0), "=r"(r1), "=r"(r2), "=r"(r3) : "r"(addr));
}
__device__ __forceinline__ void mma16816(float& d0, float& d1, float& d2, float& d3,
                                         uint32_t a0, uint32_t a1, uint32_t a2, uint32_t a3,
                                         uint32_t b0, uint32_t b1) {
    asm volatile("mma.sync.aligned.m16n8k16.row.col.f32.bf16.bf16.f32 "
                 "{%0,%1,%2,%3},{%4,%5,%6,%7},{%8,%9},{%0,%1,%2,%3};\n"
                 : "+f"(d0), "+f"(d1), "+f"(d2), "+f"(d3)
                 : "r"(a0), "r"(a1), "r"(a2), "r"(a3), "r"(b0), "r"(b1));
}
#define SW128(x) ((x) ^ (((x) >> 3) & 0x70))
__device__ __forceinline__ uint32_t f2key(float f) {
    uint32_t u = __float_as_uint(f);
    return (u & 0x80000000u) ? ~u : (u | 0x80000000u);
}

// ---------------- merged prep: weights/content + hologram fp32 -> bf16 ----------------
__global__ __launch_bounds__(256) void prep_all_kernel(
    const float* __restrict__ in_w,
    const float* __restrict__ out_w,
    const float* __restrict__ content,
    const float* __restrict__ holo)
{
    if (blockIdx.x < PREPW_BLOCKS) {
        int idx = blockIdx.x * 256 + threadIdx.x;   // 0..65535
        int d = idx >> 8;
        int e = idx & 255;
        g_wqT[e * Dm + d] = in_w[(size_t)d * Dm + e];
        g_wkT[e * Dm + d] = in_w[(size_t)(Dm + d) * Dm + e];
        g_wvT[e * Dm + d] = in_w[(size_t)(2 * Dm + d) * Dm + e];
        g_woT[e * Dm + d] = out_w[(size_t)d * Dm + e];
        g_Abf[idx] = __float2bfloat16(content[idx]);
        return;
    }
    size_t g = (size_t)(blockIdx.x - PREPW_BLOCKS) * 256 + threadIdx.x;
    size_t e = g * 8;
    if (e >= PADROWS * Dm) return;
    uint4 w;
    if (e < (size_t)CAP * Dm) {
        float4 f0 = *(const float4*)(holo + e);
        float4 f1 = *(const float4*)(holo + e + 4);
        __nv_bfloat162 p0 = __float22bfloat162_rn(make_float2(f0.x, f0.y));
        __nv_bfloat162 p1 = __float22bfloat162_rn(make_float2(f0.z, f0.w));
        __nv_bfloat162 p2 = __float22bfloat162_rn(make_float2(f1.x, f1.y));
        __nv_bfloat162 p3 = __float22bfloat162_rn(make_float2(f1.z, f1.w));
        w.x = *(uint32_t*)&p0; w.y = *(uint32_t*)&p1;
        w.z = *(uint32_t*)&p2; w.w = *(uint32_t*)&p3;
    } else {
        w = make_uint4(0u, 0u, 0u, 0u);
    }
    *(uint4*)(g_holoBf + e) = w;
}

// ---------------- pass 1: bf16 mma.sync sims GEMM + per-tile top-4 ----------------
__global__ __launch_bounds__(256, 2) void sims_mma_kernel(
    const float* __restrict__ strengths)
{
    extern __shared__ char sm[];
    const uint32_t smu = smem_u32(sm);

    const int tid  = threadIdx.x;
    const int lane = tid & 31;
    const int warp = tid >> 5;
    const int wm = warp >> 2;        // 0..1
    const int wn = warp & 3;         // 0..3
    const int m0 = blockIdx.x * 128;
    const int n0 = blockIdx.y * BN3;
    const int tileIdx = blockIdx.y;

    float acc[4][4][4];
    #pragma unroll
    for (int a = 0; a < 4; a++)
        #pragma unroll
        for (int b = 0; b < 4; b++)
            #pragma unroll
            for (int q = 0; q < 4; q++) acc[a][b][q] = 0.f;

    auto loadChunk = [&](int kc) {
        const int buf = kc % NSTG;
        const uint32_t sb = smu + buf * STG_BYTES;
        #pragma unroll
        for (int o = 0; o < 4; o++) {
            int e = o * 256 + tid;      // 0..1023
            int r = e >> 3, seg = e & 7;
            uint32_t sw = SW128((uint32_t)(r * 128 + seg * 16));
            cp16(sb + sw, g_Abf + (size_t)(m0 + r) * Dm + kc * 64 + seg * 8);
        }
        #pragma unroll
        for (int o = 0; o < 4; o++) {
            int e = o * 256 + tid;
            int r = e >> 3, seg = e & 7;
            uint32_t sw = SW128((uint32_t)(r * 128 + seg * 16));
            cp16(sb + 16384 + sw, g_holoBf + (size_t)(n0 + r) * Dm + kc * 64 + seg * 8);
        }
    };

    loadChunk(0); asm volatile("cp.async.commit_group;\n");
    loadChunk(1); asm volatile("cp.async.commit_group;\n");
    loadChunk(2); asm volatile("cp.async.commit_group;\n");

    #pragma unroll 1
    for (int kc = 0; kc < NCHK; kc++) {
        const int buf = kc % NSTG;
        const uint32_t aBase = smu + buf * STG_BYTES;
        const uint32_t bBase = aBase + 16384;
        asm volatile("cp.async.wait_group %0;\n" :: "n"(NSTG - 1));
        __syncthreads();

        #pragma unroll
        for (int k16 = 0; k16 < 4; k16++) {
            uint32_t bfr[4][2];
            #pragma unroll
            for (int p = 0; p < 2; p++) {
                int n    = p * 16 + ((lane >> 4) << 3) + (lane & 7);
                int kcol = k16 * 16 + (((lane >> 3) & 1) << 3);
                uint32_t byte = (uint32_t)((wn * 32 + n) * 128 + kcol * 2);
                ldsm4(bfr[p * 2][0], bfr[p * 2][1], bfr[p * 2 + 1][0], bfr[p * 2 + 1][1],
                      bBase + SW128(byte));
            }
            uint32_t afr[4][4];
            #pragma unroll
            for (int mf = 0; mf < 4; mf++) {
                int r    = wm * 64 + mf * 16 + (((lane >> 3) & 1) << 3) + (lane & 7);
                int kcol = k16 * 16 + ((lane >> 4) << 3);
                uint32_t byte = (uint32_t)(r * 128 + kcol * 2);
                ldsm4(afr[mf][0], afr[mf][1], afr[mf][2], afr[mf][3], aBase + SW128(byte));
            }
            #pragma unroll
            for (int mf = 0; mf < 4; mf++)
                #pragma unroll
                for (int nf = 0; nf < 4; nf++)
                    mma16816(acc[mf][nf][0], acc[mf][nf][1], acc[mf][nf][2], acc[mf][nf][3],
                             afr[mf][0], afr[mf][1], afr[mf][2], afr[mf][3],
                             bfr[nf][0], bfr[nf][1]);
        }
        __syncthreads();
        if (kc + NSTG < NCHK) loadChunk(kc + NSTG);
        asm volatile("cp.async.commit_group;\n");
    }

    // ---------------- epilogue: per-row top-4 ----------------
    float* Ds   = (float*)(sm + OFF_DS);
    float* sLv  = (float*)(sm + OFF_LV);
    int*   sLi  = (int*)(sm + OFF_LI);
    float* sStr = (float*)(sm + OFF_STR);

    if (tid < BN3) {
        int gc = n0 + tid;
        sStr[tid] = (gc < CAP) ? strengths[gc] : 0.f;
    }

    #pragma unroll
    for (int mf = 0; mf < 4; mf++)
        #pragma unroll
        for (int nf = 0; nf < 4; nf++) {
            int r = wm * 64 + mf * 16 + (lane >> 2);
            int c = wn * 32 + nf * 8 + (lane & 3) * 2;
            *(float2*)(Ds + r * 132 + c)       = make_float2(acc[mf][nf][0], acc[mf][nf][1]);
            *(float2*)(Ds + (r + 8) * 132 + c) = make_float2(acc[mf][nf][2], acc[mf][nf][3]);
        }
    __syncthreads();

    {
        int r = tid >> 1, hc = tid & 1;
        float v[TCAND]; int id[TCAND];
        #pragma unroll
        for (int t = 0; t < TCAND; t++) { v[t] = -INFINITY; id[t] = 0x7fffffff; }
        const float* row = Ds + r * 132 + hc * 64;
        int cb = hc * 64;
        #pragma unroll 4
        for (int j = 0; j < 64; j++) {
            int c = cb + j;
            int gc = n0 + c;
            float val = row[j] * sStr[c];
            if (gc < CAP && val > v[TCAND - 1]) {     // strict >: ascending col keeps lowest idx
                v[TCAND - 1] = val; id[TCAND - 1] = gc;
                #pragma unroll
                for (int p = TCAND - 1; p > 0; p--) {
                    if (v[p] > v[p - 1]) {
                        float tv = v[p]; v[p] = v[p - 1]; v[p - 1] = tv;
                        int ti = id[p]; id[p] = id[p - 1]; id[p - 1] = ti;
                    }
                }
            }
        }
        #pragma unroll
        for (int t = 0; t < TCAND; t++) { sLv[tid * TCAND + t] = v[t]; sLi[tid * TCAND + t] = id[t]; }
    }
    __syncthreads();

    if (tid < 128) {
        const float* va = sLv + (2 * tid) * TCAND;
        const int*   ia = sLi + (2 * tid) * TCAND;
        const float* vb = sLv + (2 * tid + 1) * TCAND;
        const int*   ib = sLi + (2 * tid + 1) * TCAND;
        float mv[TCAND]; int mi[TCAND];
        int pa = 0, pb = 0;
        #pragma unroll
        for (int t = 0; t < TCAND; t++) {
            bool takeA = (va[pa] >= vb[pb]);   // A = lower cols -> lower idx on tie
            mv[t] = takeA ? va[pa] : vb[pb];
            mi[t] = takeA ? ia[pa] : ib[pb];
            if (takeA) pa++; else pb++;
        }
        size_t base = ((size_t)(m0 + tid) * NTILE + tileIdx) * TCAND;
        *(float4*)(g_candV + base) = make_float4(mv[0], mv[1], mv[2], mv[3]);
        *(int4*)(g_candI + base)   = make_int4(mi[0], mi[1], mi[2], mi[3]);
    }
}

// ---------------- fused: radix-select window + exact fp32 rescore + top-10 ----------------
// One CTA per content row. Window indices never leave smem.
__global__ __launch_bounds__(256) void select_rescore_kernel(
    const float* __restrict__ content,
    const float* __restrict__ holo,
    const float* __restrict__ strengths)
{
    extern __shared__ uint32_t skeys[];        // TOTC keys = 62512 bytes
    __shared__ uint32_t hist[256];
    __shared__ uint32_t sPrefix;
    __shared__ uint32_t sR;
    __shared__ int      sCount;
    __shared__ float cont[Dm];
    __shared__ int   winI[WCAP];
    __shared__ float sv[WCAP];
    __shared__ int   sid[WCAP];

    const int row = blockIdx.x;
    const int tid = threadIdx.x;
    const int lane = tid & 31, warp = tid >> 5;
    const size_t base = (size_t)row * TOTC;

    if (tid == 0) { sPrefix = 0u; sR = SELR; sCount = 0; }
    if (tid < WCAP) winI[tid] = 0x7fffffff;
    cont[tid] = content[(size_t)row * Dm + tid];
    hist[tid] = 0u;
    __syncthreads();

    // pass 1 (shift 24): global load + cache + histogram
    for (int i = tid; i < TOTC; i += 256) {
        uint32_t key = f2key(g_candV[base + i]);
        skeys[i] = key;
        atomicAdd(&hist[key >> 24], 1u);
    }
    __syncthreads();

    #pragma unroll 1
    for (int shift = 24; shift >= 8; shift -= 8) {
        if (tid < 32) {
            uint32_t h[8];
            uint32_t s = 0;
            #pragma unroll
            for (int j = 0; j < 8; j++) { h[j] = hist[255 - tid * 8 - j]; s += h[j]; }
            uint32_t pre = s;
            #pragma unroll
            for (int o = 1; o < 32; o <<= 1) {
                uint32_t t2 = __shfl_up_sync(0xffffffffu, pre, o);
                if (tid >= o) pre += t2;
            }
            pre -= s;
            const uint32_t R = sR;
            if (pre < R && pre + s >= R) {
                uint32_t cum = pre;
                #pragma unroll
                for (int j = 0; j < 8; j++) {
                    int b = 255 - tid * 8 - j;
                    if (cum + h[j] >= R) {
                        sPrefix = sPrefix | ((uint32_t)b << shift);
                        sR = R - cum;
                        break;
                    }
                    cum += h[j];
                }
            }
        }
        __syncthreads();

        if (shift > 8) {
            hist[tid] = 0u;
            __syncthreads();
            const int nshift = shift - 8;
            const uint32_t maskFixed = 0xFFFFFFFFu << shift;
            const uint32_t prefix = sPrefix;
            for (int i = tid; i < TOTC; i += 256) {
                uint32_t key = skeys[i];
                if ((key & maskFixed) == prefix)
                    atomicAdd(&hist[(key >> nshift) & 255u], 1u);
            }
            __syncthreads();
        }
    }

    const uint32_t T = sPrefix;   // 24-bit-resolved threshold (<= exact 24th key)
    for (int i = tid; i < TOTC; i += 256) {
        if (skeys[i] >= T) {
            int slot = atomicAdd(&sCount, 1);
            if (slot < WCAP) winI[slot] = g_candI[base + i];
        }
    }
    __syncthreads();

    // ---- exact fp32 rescore of the window ----
    for (int c = warp; c < WCAP; c += 8) {
        int idx = winI[c];
        float part = 0.f;
        if (idx < CAP) {
            const float* hp = holo + (size_t)idx * Dm + lane * 8;
            const float* cp = cont + lane * 8;
            float4 h0 = *(const float4*)hp;
            float4 h1 = *(const float4*)(hp + 4);
            part = h0.x * cp[0] + h0.y * cp[1] + h0.z * cp[2] + h0.w * cp[3]
                 + h1.x * cp[4] + h1.y * cp[5] + h1.z * cp[6] + h1.w * cp[7];
        }
        #pragma unroll
        for (int s = 16; s >= 1; s >>= 1) part += __shfl_xor_sync(0xffffffffu, part, s);
        if (lane == 0) {
            sv[c]  = (idx < CAP) ? part * strengths[idx] : -INFINITY;
            sid[c] = idx;
        }
    }
    __syncthreads();

    if (tid == 0) {
        float w[KTOP]; int wi[KTOP];
        #pragma unroll
        for (int t = 0; t < KTOP; t++) { w[t] = -INFINITY; wi[t] = 0x7fffffff; }
        for (int e = 0; e < WCAP; e++) {
            float nv = sv[e]; int ni = sid[e];
            if (nv > w[KTOP - 1] || (nv == w[KTOP - 1] && ni < wi[KTOP - 1])) {
                w[KTOP - 1] = nv; wi[KTOP - 1] = ni;
                #pragma unroll
                for (int p = KTOP - 1; p > 0; p--) {
                    if (w[p] > w[p - 1] || (w[p] == w[p - 1] && wi[p] < wi[p - 1])) {
                        float tv = w[p]; w[p] = w[p - 1]; w[p - 1] = tv;
                        int ti = wi[p]; wi[p] = wi[p - 1]; wi[p - 1] = ti;
                    }
                }
            }
        }
        for (int t = 0; t < KTOP; t++) g_topIdx[row * KTOP + t] = wi[t];
    }
}

// ---------------- fused: q/k/v projections + attention + out proj (per batch) ----------------
__global__ __launch_bounds__(256) void qkv_attn_kernel(
    const float* __restrict__ content,
    const float* __restrict__ holo,
    const float* __restrict__ in_b,
    const float* __restrict__ out_b,
    float* __restrict__ out)
{
    __shared__ float cont[Dm];
    __shared__ float rows[KTOP][Dm];
    __shared__ float qs[Dm];
    __shared__ float ks[KTOP][Dm];
    __shared__ float vs[KTOP][Dm];
    __shared__ float attnS[Hh][KTOP];
    __shared__ float ctxS[Dm];

    const int b = blockIdx.x;
    const int tid = threadIdx.x;

    cont[tid] = content[(size_t)b * Dm + tid];
    for (int i = tid; i < KTOP * Dm; i += 256) {
        int kk = i >> 8;
        int c = i & 255;
        int hid = g_topIdx[b * KTOP + kk];
        rows[kk][c] = holo[(size_t)hid * Dm + c];
    }
    __syncthreads();

    // q / k / v projections (same loop order as the separate kernels)
    {
        const int d = tid;
        float qa = 0.f;
        float ka[KTOP], va[KTOP];
        #pragma unroll
        for (int j = 0; j < KTOP; j++) { ka[j] = 0.f; va[j] = 0.f; }
        for (int e = 0; e < Dm; e++) {
            float wq = g_wqT[e * Dm + d];
            float wk = g_wkT[e * Dm + d];
            float wv = g_wvT[e * Dm + d];
            qa = fmaf(cont[e], wq, qa);
            #pragma unroll
            for (int j = 0; j < KTOP; j++) {
                float rv = rows[j][e];
                ka[j] = fmaf(rv, wk, ka[j]);
                va[j] = fmaf(rv, wv, va[j]);
            }
        }
        qs[d] = qa + in_b[d];
        float bk = in_b[Dm + d];
        float bv2 = in_b[2 * Dm + d];
        #pragma unroll
        for (int j = 0; j < KTOP; j++) {
            ks[j][d] = ka[j] + bk;
            vs[j][d] = va[j] + bv2;
        }
    }
    __syncthreads();

    if (tid < Hh * KTOP) {
        int h = tid / KTOP, kk = tid % KTOP;
        float s = 0.f;
        #pragma unroll
        for (int d2 = 0; d2 < HD; d2++)
            s = fmaf(qs[h * HD + d2], ks[kk][h * HD + d2], s);
        attnS[h][kk] = s * 0.17677669529663687f;  // 1/sqrt(32)
    }
    __syncthreads();

    if (tid < Hh) {
        int h = tid;
        float mx = -INFINITY;
        for (int kk = 0; kk < KTOP; kk++) mx = fmaxf(mx, attnS[h][kk]);
        float sum = 0.f;
        for (int kk = 0; kk < KTOP; kk++) {
            float e2 = expf(attnS[h][kk] - mx);
            attnS[h][kk] = e2;
            sum += e2;
        }
        float inv = 1.f / sum;
        for (int kk = 0; kk < KTOP; kk++) attnS[h][kk] *= inv;
    }
    __syncthreads();

    if (tid < KTOP) {
        float m = 0.f;
        for (int h = 0; h < Hh; h++) m += attnS[h][tid];
        out[(size_t)Bsz * Dm + (size_t)b * KTOP + tid] = m * 0.125f;
    }

    {
        int d2 = tid, h = d2 >> 5;
        float c = 0.f;
        #pragma unroll
        for (int kk = 0; kk < KTOP; kk++)
            c = fmaf(attnS[h][kk], vs[kk][d2], c);
        ctxS[d2] = c;
    }
    __syncthreads();

    float r = 0.f;
    for (int e = 0; e < Dm; e++)
        r = fmaf(ctxS[e], g_woT[e * Dm + tid], r);
    out[(size_t)b * Dm + tid] = r + out_b[tid];
}

// ---------------- launch ----------------
extern "C" void kernel_launch(void* const* d_in, const int* in_sizes, int n_in,
                              void* d_out, int out_size)
{
    const float* content   = (const float*)d_in[0];
    const float* hologram  = (const float*)d_in[1];
    const float* strengths = (const float*)d_in[2];
    const float* in_w      = (const float*)d_in[3];
    const float* in_b      = (const float*)d_in[4];
    const float* out_w     = (const float*)d_in[5];
    const float* out_b     = (const float*)d_in[6];
    float* out = (float*)d_out;

    cudaFuncSetAttribute(sims_mma_kernel,
                         cudaFuncAttributeMaxDynamicSharedMemorySize, SMEM3);
    cudaFuncSetAttribute(select_rescore_kernel,
                         cudaFuncAttributeMaxDynamicSharedMemorySize, SEL_SMEM);

    {
        size_t nvec = PADROWS * Dm / 8;
        unsigned holoBlocks = (unsigned)((nvec + 255) / 256);
        prep_all_kernel<<<PREPW_BLOCKS + holoBlocks, 256>>>(in_w, out_w, content, hologram);
    }

    dim3 g1(2, NTILE);
    sims_mma_kernel<<<g1, 256, SMEM3>>>(strengths);

    select_rescore_kernel<<<Bsz, 256, SEL_SMEM>>>(content, hologram, strengths);

    qkv_attn_kernel<<<Bsz, 256>>>(content, hologram, in_b, out_b, out);
}